// round 16
// baseline (speedup 1.0000x reference)
#include <cuda_runtime.h>
#include <mma.h>
#include <string.h>
#include <stdint.h>
using namespace nvcuda;

#define N_TOK   32768
#define K_CODE  8192
#define D_DIM   64

#define ZQ_OFF   0
#define LOSS_OFF 2097152
#define IDX_OFF  2097153
#define CSN_OFF  (2097153 + 32768)
#define EMA_OFF  (2129921 + 8192)
#define EMB_OFF  (2138113 + 524288)

#define DECAYF   0.99f
#define OMDF     0.00999999977648258209228515625f
#define EPSF     1e-5f
#define KEPSF    0.08192f
#define BETAF    0.25f

// smem float offsets for k_main
#define SM_B0    0        // 8192 f  (eh 4096 | el 4096) chunk buf 0
#define SM_B1    8192     // 8192 f  buf 1
#define SM_BIAS  16384    // 8192 f
#define SM_SC    24576    // 9216 f  (8 warps x 32 rows x 36)
#define SM_TOTF  33792    // 135168 bytes

// ---------------- device scratch ----------------
__device__ float g_zh[2097152];   // [token][dim] tf32-hi(z)
__device__ float g_zl[2097152];   // [token][dim] tf32(z - hi)
__device__ float g_eh[524288];    // [code][dim]  tf32-hi(emb)
__device__ float g_el[524288];    // [code][dim]  tf32(emb - hi)
__device__ float g_bias[K_CODE];
__device__ int   g_idx[N_TOK];
__device__ int   g_counts[K_CODE];
__device__ float g_sumw[K_CODE * D_DIM];
__device__ float g_cs[K_CODE];
__device__ float g_cssum;
__device__ float g_loss;

// ---------------- helpers ----------------
__device__ __forceinline__ void cp16(void* dst, const void* src) {
    unsigned sa = (unsigned)__cvta_generic_to_shared(dst);
    asm volatile("cp.async.cg.shared.global [%0], [%1], 16;" :: "r"(sa), "l"(src));
}
__device__ __forceinline__ float tf32r(float v) {    // round-to-nearest tf32
    uint32_t h;
    asm("cvt.rna.tf32.f32 %0, %1;" : "=r"(h) : "f"(v));
    return __uint_as_float(h);
}
__device__ __forceinline__ void block_atomic_add(float v, float* target) {
    #pragma unroll
    for (int m = 16; m >= 1; m >>= 1) v += __shfl_xor_sync(0xffffffffu, v, m);
    __shared__ float red[8];
    int w = threadIdx.x >> 5;
    if ((threadIdx.x & 31) == 0) red[w] = v;
    __syncthreads();
    if (threadIdx.x == 0) {
        float s = 0.f;
        #pragma unroll
        for (int i = 0; i < 8; i++) s += red[i];
        atomicAdd(target, s);
    }
}

// ---------------- K_prep: planes + bias + zero (grid-switched) --------------
// [0,8192): z planes; [8192,10240): e planes; [10240,10272): bias; rest zero
__global__ void k_prep(const float* __restrict__ z, const float* __restrict__ emb) {
    int blk = blockIdx.x;
    if (blk < 8192) {
        int gid = blk * 256 + threadIdx.x;          // coalesced z read (NCHW)
        float v = z[gid];
        int b = gid >> 16, d = (gid >> 10) & 63, hw = gid & 1023;
        int n = (b << 10) | hw;
        float hi = tf32r(v);
        size_t o = (size_t)n * 64 + d;
        g_zh[o] = hi;
        g_zl[o] = tf32r(v - hi);
    } else if (blk < 10240) {
        int gid = (blk - 8192) * 256 + threadIdx.x; // same layout as emb
        float v = emb[gid];
        float hi = tf32r(v);
        g_eh[gid] = hi;
        g_el[gid] = tf32r(v - hi);
    } else if (blk < 10272) {
        int k = (blk - 10240) * 256 + threadIdx.x;
        const float4* ep = reinterpret_cast<const float4*>(emb + (size_t)k * D_DIM);
        float nrm = 0.f;
        #pragma unroll
        for (int s4 = 0; s4 < 16; s4++) {
            float4 v = ep[s4];
            nrm += v.x * v.x + v.y * v.y + v.z * v.z + v.w * v.w;
        }
        g_bias[k] = 0.5f * nrm;
    } else {
        int gid = (blk - 10272) * 256 + threadIdx.x; // 524288
        g_sumw[gid] = 0.f;
        if (gid < K_CODE) g_counts[gid] = 0;
        if (gid == 0) { g_cssum = 0.f; g_loss = 0.f; }
    }
}

// ---------------- K_main: wmma tf32 3-split GEMM + fused argmax -------------
// 256 CTAs x 256 thr. Warp (mw = wid>>1, nh = wid&1): rows [mt*128+32mw, +32),
// cols [nh*32, +32) of each 64-code chunk. A frags (hi+lo, 32) preloaded into
// registers from global planes. B chunk (64 codes, hi+lo = 32KB) cp.async
// double-buffered. Scores via store_matrix_sync to warp-private smem patch;
// lane l owns token row l: ascending-code scan, strict '>' == jnp.argmin.
__global__ void __launch_bounds__(256) k_main(float* __restrict__ out) {
    extern __shared__ float smf[];
    const int tid = threadIdx.x;
    const int wid = tid >> 5, lane = tid & 31;
    const int mw = wid >> 1, nh = wid & 1;
    const int mt = blockIdx.x;
    const int r0 = mt * 128 + mw * 32;

    // prologue: bias (32KB) + chunk 0 (32KB)
    #pragma unroll
    for (int r = 0; r < 8; r++)
        cp16((char*)(smf + SM_BIAS) + (tid + r * 256) * 16, (const char*)g_bias + (tid + r * 256) * 16);
    #pragma unroll
    for (int r = 0; r < 4; r++) {
        cp16((char*)(smf + SM_B0) + (tid + r * 256) * 16, (const char*)g_eh + (tid + r * 256) * 16);
        cp16((char*)(smf + SM_B0 + 4096) + (tid + r * 256) * 16, (const char*)g_el + (tid + r * 256) * 16);
    }
    asm volatile("cp.async.commit_group;");

    // A fragments once from global (compiler-owned layout)
    wmma::fragment<wmma::matrix_a, 16, 16, 8, wmma::precision::tf32, wmma::row_major> ah[8][2], al[8][2];
    #pragma unroll
    for (int k8 = 0; k8 < 8; k8++)
        #pragma unroll
        for (int mf = 0; mf < 2; mf++) {
            wmma::load_matrix_sync(ah[k8][mf], g_zh + (size_t)(r0 + 16 * mf) * 64 + k8 * 8, 64);
            wmma::load_matrix_sync(al[k8][mf], g_zl + (size_t)(r0 + 16 * mf) * 64 + k8 * 8, 64);
        }

    float* patch = smf + SM_SC + wid * 1152;   // 32 rows x ldm 36
    float bs = -3.4e38f;
    int   bi = 0;

    for (int ch = 0; ch < 128; ++ch) {
        const int buf = ch & 1;
        if (ch + 1 < 128) {
            float* dst = smf + ((ch + 1) & 1 ? SM_B1 : SM_B0);
            const float* sh = g_eh + (size_t)(ch + 1) * 4096;
            const float* sl = g_el + (size_t)(ch + 1) * 4096;
            #pragma unroll
            for (int r = 0; r < 4; r++) {
                cp16((char*)dst + (tid + r * 256) * 16, (const char*)sh + (tid + r * 256) * 16);
                cp16((char*)(dst + 4096) + (tid + r * 256) * 16, (const char*)sl + (tid + r * 256) * 16);
            }
            asm volatile("cp.async.commit_group;");
            asm volatile("cp.async.wait_group 1;");
        } else {
            asm volatile("cp.async.wait_group 0;");
        }
        __syncthreads();

        const float* Bh = smf + (buf ? SM_B1 : SM_B0) + nh * 32 * 64;  // 32 codes col-major (ldm=64)
        const float* Bl = Bh + 4096;

        wmma::fragment<wmma::accumulator, 16, 16, 8, float> acc[2][2];
        #pragma unroll
        for (int mf = 0; mf < 2; mf++)
            #pragma unroll
            for (int nf = 0; nf < 2; nf++)
                wmma::fill_fragment(acc[mf][nf], 0.0f);

        #pragma unroll
        for (int k8 = 0; k8 < 8; k8++) {
            wmma::fragment<wmma::matrix_b, 16, 16, 8, wmma::precision::tf32, wmma::col_major> bh[2], bl[2];
            #pragma unroll
            for (int nf = 0; nf < 2; nf++) {
                wmma::load_matrix_sync(bh[nf], Bh + nf * 16 * 64 + k8 * 8, 64);
                wmma::load_matrix_sync(bl[nf], Bl + nf * 16 * 64 + k8 * 8, 64);
            }
            #pragma unroll
            for (int mf = 0; mf < 2; mf++)
                #pragma unroll
                for (int nf = 0; nf < 2; nf++) {
                    wmma::mma_sync(acc[mf][nf], ah[k8][mf], bh[nf], acc[mf][nf]);
                    wmma::mma_sync(acc[mf][nf], al[k8][mf], bh[nf], acc[mf][nf]);
                    wmma::mma_sync(acc[mf][nf], ah[k8][mf], bl[nf], acc[mf][nf]);
                }
        }

        // scores -> warp-private smem, then per-lane row scan
        #pragma unroll
        for (int mf = 0; mf < 2; mf++)
            #pragma unroll
            for (int nf = 0; nf < 2; nf++)
                wmma::store_matrix_sync(patch + mf * 16 * 36 + nf * 16, acc[mf][nf], 36, wmma::mem_row_major);
        __syncwarp();

        const float* rowp  = patch + lane * 36;
        const float* biasp = smf + SM_BIAS + ch * 64 + nh * 32;
        #pragma unroll
        for (int c = 0; c < 32; c++) {
            float sc = rowp[c] - biasp[c];
            if (sc > bs) { bs = sc; bi = ch * 64 + nh * 32 + c; }
        }
        __syncthreads();
    }

    // merge the two n-halves per token (smem reuse of scores area)
    float* mS = smf + SM_SC;                 // [128][2] score
    int*   mI = (int*)(smf + SM_SC + 256);   // [128][2] code
    mS[(mw * 32 + lane) * 2 + nh] = bs;
    mI[(mw * 32 + lane) * 2 + nh] = bi;
    __syncthreads();
    if (tid < 128) {
        float s0 = mS[tid * 2], s1 = mS[tid * 2 + 1];
        int   c0 = mI[tid * 2], c1 = mI[tid * 2 + 1];
        int c = (s1 > s0 || (s1 == s0 && c1 < c0)) ? c1 : c0;
        int token = mt * 128 + tid;
        g_idx[token] = c;
        out[IDX_OFF + token] = (float)c;
    }
}

// ---------------- K2b: counts + segment-sum of z (reads z NCHW) -------------
__global__ void k_finalize(const float* __restrict__ z) {
    int n = blockIdx.x * 256 + threadIdx.x;     // 32768 threads
    int code = g_idx[n];
    atomicAdd(&g_counts[code], 1);
    int b = n >> 10, hw = n & 1023;
    const float* zp = z + (size_t)b * 65536 + hw;
    float* sw = g_sumw + (size_t)code * D_DIM;
    #pragma unroll
    for (int d = 0; d < 64; d++)
        atomicAdd(&sw[d], zp[(size_t)d * 1024]);
}

// ---------------- K3: gather z_q (NCHW) + commitment loss -------------------
__global__ void k_gather(const float* __restrict__ z, const float* __restrict__ emb,
                         float* __restrict__ out) {
    int gid = blockIdx.x * 256 + threadIdx.x;
    int b = gid >> 16, c = (gid >> 10) & 63, hw = gid & 1023;
    int n = (b << 10) | hw;
    int code = g_idx[n];
    float q  = __ldg(&emb[(size_t)code * D_DIM + c]);
    float zv = z[gid];
    float d  = q - zv;
    out[ZQ_OFF + gid] = zv + d;
    block_atomic_add(d * d, &g_loss);
}

// ---------------- K4a ----------------
__global__ void k_cs(const float* __restrict__ cs_in) {
    int k = blockIdx.x * 256 + threadIdx.x;
    float c = DECAYF * cs_in[k] + OMDF * (float)g_counts[k];
    g_cs[k] = c;
    block_atomic_add(c, &g_cssum);
}

// ---------------- K4b ----------------
__global__ void k_out(const float* __restrict__ ema_w, float* __restrict__ out) {
    int gid = blockIdx.x * 256 + threadIdx.x;
    int k = gid >> 6, d = gid & 63;
    float denom = g_cssum + KEPSF;
    float cn = (g_cs[k] + EPSF) / denom;
    float ew = DECAYF * ema_w[gid] + OMDF * g_sumw[gid];
    out[EMA_OFF + gid] = ew;
    out[EMB_OFF + gid] = ew / cn;
    if (d == 0)   out[CSN_OFF + k] = cn;
    if (gid == 0) out[LOSS_OFF] = BETAF * g_loss * (1.0f / 2097152.0f);
}

// ---------------- launch ----------------
extern "C" void kernel_launch(void* const* d_in, const int* in_sizes, int n_in,
                              void* d_out, int out_size) {
    const float* z      = (const float*)d_in[0];
    const float* emb    = (const float*)d_in[1];
    const float* ema_w  = (const float*)d_in[2];
    const float* cs_in  = (const float*)d_in[3];
    float* out = (float*)d_out;

    const int SMEM_MAIN = SM_TOTF * 4;   // 135168 B
    cudaFuncSetAttribute(k_main, cudaFuncAttributeMaxDynamicSharedMemorySize, SMEM_MAIN);

    k_prep    <<<12320, 256>>>(z, emb);
    k_main    <<<  256, 256, SMEM_MAIN>>>(out);
    k_finalize<<<  128, 256>>>(z);
    k_gather  <<< 8192, 256>>>(z, emb, out);
    k_cs      <<<   32, 256>>>(cs_in);
    k_out     <<< 2048, 256>>>(ema_w, out);
}

// round 17
// speedup vs baseline: 1.7447x; 1.7447x over previous
#include <cuda_runtime.h>
#include <mma.h>
#include <string.h>
#include <stdint.h>
using namespace nvcuda;

#define N_TOK   32768
#define K_CODE  8192
#define D_DIM   64

#define ZQ_OFF   0
#define LOSS_OFF 2097152
#define IDX_OFF  2097153
#define CSN_OFF  (2097153 + 32768)
#define EMA_OFF  (2129921 + 8192)
#define EMB_OFF  (2138113 + 524288)

#define DECAYF   0.99f
#define OMDF     0.00999999977648258209228515625f
#define EPSF     1e-5f
#define KEPSF    0.08192f
#define BETAF    0.25f

// smem float offsets for k_main
#define SM_B0    0        // 8192 f  (eh 4096 | el 4096) chunk buf 0
#define SM_B1    8192     // 8192 f  buf 1
#define SM_BIAS  16384    // 8192 f
#define SM_SC    24576    // 9216 f  (8 warps x 32 rows x 36)
#define SM_TOTF  33792    // 135168 bytes

// ---------------- device scratch ----------------
__device__ float g_zh[2097152];   // [token][dim] tf32-hi(z)
__device__ float g_zl[2097152];   // [token][dim] tf32(z - hi)
__device__ float g_ehp[524288];   // [chunk 128][dim 64][code 64] tf32-hi(emb), k-major per chunk
__device__ float g_elp[524288];   // same layout, residual plane
__device__ float g_bias[K_CODE];
__device__ int   g_idx[N_TOK];
__device__ int   g_counts[K_CODE];
__device__ float g_sumw[K_CODE * D_DIM];
__device__ float g_cs[K_CODE];
__device__ float g_cssum;
__device__ float g_loss;

// ---------------- helpers ----------------
__device__ __forceinline__ void cp16(void* dst, const void* src) {
    unsigned sa = (unsigned)__cvta_generic_to_shared(dst);
    asm volatile("cp.async.cg.shared.global [%0], [%1], 16;" :: "r"(sa), "l"(src));
}
__device__ __forceinline__ float tf32r(float v) {    // round-to-nearest tf32
    uint32_t h;
    asm("cvt.rna.tf32.f32 %0, %1;" : "=r"(h) : "f"(v));
    return __uint_as_float(h);
}
__device__ __forceinline__ void block_atomic_add(float v, float* target) {
    #pragma unroll
    for (int m = 16; m >= 1; m >>= 1) v += __shfl_xor_sync(0xffffffffu, v, m);
    __shared__ float red[8];
    int w = threadIdx.x >> 5;
    if ((threadIdx.x & 31) == 0) red[w] = v;
    __syncthreads();
    if (threadIdx.x == 0) {
        float s = 0.f;
        #pragma unroll
        for (int i = 0; i < 8; i++) s += red[i];
        atomicAdd(target, s);
    }
}

// ---------------- K_prep: planes + bias + zero (grid-switched) --------------
// [0,8192): z planes; [8192,10240): e planes (dim-major per 64-code chunk);
// [10240,10272): bias; rest zero
__global__ void k_prep(const float* __restrict__ z, const float* __restrict__ emb) {
    int blk = blockIdx.x;
    if (blk < 8192) {
        int gid = blk * 256 + threadIdx.x;          // coalesced z read (NCHW)
        float v = z[gid];
        int b = gid >> 16, d = (gid >> 10) & 63, hw = gid & 1023;
        int n = (b << 10) | hw;
        float hi = tf32r(v);
        size_t o = (size_t)n * 64 + d;
        g_zh[o] = hi;
        g_zl[o] = tf32r(v - hi);
    } else if (blk < 10240) {
        int gid = (blk - 8192) * 256 + threadIdx.x; // gid = code*64 + d (coalesced read)
        float v = emb[gid];
        float hi = tf32r(v);
        int code = gid >> 6, d = gid & 63;
        // dim-major per chunk: [code>>6][d][code&63]  -> row-major [k][n] for wmma
        size_t o = (size_t)(code >> 6) * 4096 + (size_t)d * 64 + (code & 63);
        g_ehp[o] = hi;
        g_elp[o] = tf32r(v - hi);
    } else if (blk < 10272) {
        int k = (blk - 10240) * 256 + threadIdx.x;
        const float4* ep = reinterpret_cast<const float4*>(emb + (size_t)k * D_DIM);
        float nrm = 0.f;
        #pragma unroll
        for (int s4 = 0; s4 < 16; s4++) {
            float4 v = ep[s4];
            nrm += v.x * v.x + v.y * v.y + v.z * v.z + v.w * v.w;
        }
        g_bias[k] = 0.5f * nrm;
    } else {
        int gid = (blk - 10272) * 256 + threadIdx.x; // 524288
        g_sumw[gid] = 0.f;
        if (gid < K_CODE) g_counts[gid] = 0;
        if (gid == 0) { g_cssum = 0.f; g_loss = 0.f; }
    }
}

// ---------------- K_main: wmma tf32 3-split GEMM + fused argmax -------------
// 256 CTAs x 256 thr. Warp (mw = wid>>1, nh = wid&1): rows [mt*128+32mw, +32),
// cols [nh*32, +32) of each 64-code chunk. A frags (hi+lo, 32) preloaded into
// registers from global planes. B chunk (64 dims x 64 codes, hi+lo = 32KB)
// cp.async double-buffered; row-major [k][n] layout -> conflict-free B frag
// loads. Scores via store_matrix_sync to warp-private smem patch; lane l owns
// token row l: ascending-code scan, strict '>' == jnp.argmin.
__global__ void __launch_bounds__(256) k_main(float* __restrict__ out) {
    extern __shared__ float smf[];
    const int tid = threadIdx.x;
    const int wid = tid >> 5, lane = tid & 31;
    const int mw = wid >> 1, nh = wid & 1;
    const int mt = blockIdx.x;
    const int r0 = mt * 128 + mw * 32;

    // prologue: bias (32KB) + chunk 0 (32KB)
    #pragma unroll
    for (int r = 0; r < 8; r++)
        cp16((char*)(smf + SM_BIAS) + (tid + r * 256) * 16, (const char*)g_bias + (tid + r * 256) * 16);
    #pragma unroll
    for (int r = 0; r < 4; r++) {
        cp16((char*)(smf + SM_B0) + (tid + r * 256) * 16, (const char*)g_ehp + (tid + r * 256) * 16);
        cp16((char*)(smf + SM_B0 + 4096) + (tid + r * 256) * 16, (const char*)g_elp + (tid + r * 256) * 16);
    }
    asm volatile("cp.async.commit_group;");

    // A fragments once from global (compiler-owned layout)
    wmma::fragment<wmma::matrix_a, 16, 16, 8, wmma::precision::tf32, wmma::row_major> ah[8][2], al[8][2];
    #pragma unroll
    for (int k8 = 0; k8 < 8; k8++)
        #pragma unroll
        for (int mf = 0; mf < 2; mf++) {
            wmma::load_matrix_sync(ah[k8][mf], g_zh + (size_t)(r0 + 16 * mf) * 64 + k8 * 8, 64);
            wmma::load_matrix_sync(al[k8][mf], g_zl + (size_t)(r0 + 16 * mf) * 64 + k8 * 8, 64);
        }

    float* patch = smf + SM_SC + wid * 1152;   // 32 rows x ldm 36
    float bs = -3.4e38f;
    int   bi = 0;

    for (int ch = 0; ch < 128; ++ch) {
        const int buf = ch & 1;
        if (ch + 1 < 128) {
            float* dst = smf + ((ch + 1) & 1 ? SM_B1 : SM_B0);
            const float* sh = g_ehp + (size_t)(ch + 1) * 4096;
            const float* sl = g_elp + (size_t)(ch + 1) * 4096;
            #pragma unroll
            for (int r = 0; r < 4; r++) {
                cp16((char*)dst + (tid + r * 256) * 16, (const char*)sh + (tid + r * 256) * 16);
                cp16((char*)(dst + 4096) + (tid + r * 256) * 16, (const char*)sl + (tid + r * 256) * 16);
            }
            asm volatile("cp.async.commit_group;");
            asm volatile("cp.async.wait_group 1;");
        } else {
            asm volatile("cp.async.wait_group 0;");
        }
        __syncthreads();

        // row-major B: [k=64][n=64], this warp's n-offset = nh*32
        const float* Bh = smf + (buf ? SM_B1 : SM_B0) + nh * 32;
        const float* Bl = Bh + 4096;

        wmma::fragment<wmma::accumulator, 16, 16, 8, float> acc[2][2];
        #pragma unroll
        for (int mf = 0; mf < 2; mf++)
            #pragma unroll
            for (int nf = 0; nf < 2; nf++)
                wmma::fill_fragment(acc[mf][nf], 0.0f);

        #pragma unroll
        for (int k8 = 0; k8 < 8; k8++) {
            wmma::fragment<wmma::matrix_b, 16, 16, 8, wmma::precision::tf32, wmma::row_major> bh[2], bl[2];
            #pragma unroll
            for (int nf = 0; nf < 2; nf++) {
                wmma::load_matrix_sync(bh[nf], Bh + (size_t)(k8 * 8) * 64 + nf * 16, 64);
                wmma::load_matrix_sync(bl[nf], Bl + (size_t)(k8 * 8) * 64 + nf * 16, 64);
            }
            #pragma unroll
            for (int mf = 0; mf < 2; mf++)
                #pragma unroll
                for (int nf = 0; nf < 2; nf++) {
                    wmma::mma_sync(acc[mf][nf], ah[k8][mf], bh[nf], acc[mf][nf]);
                    wmma::mma_sync(acc[mf][nf], al[k8][mf], bh[nf], acc[mf][nf]);
                    wmma::mma_sync(acc[mf][nf], ah[k8][mf], bl[nf], acc[mf][nf]);
                }
        }

        // scores -> warp-private smem, then per-lane row scan
        #pragma unroll
        for (int mf = 0; mf < 2; mf++)
            #pragma unroll
            for (int nf = 0; nf < 2; nf++)
                wmma::store_matrix_sync(patch + mf * 16 * 36 + nf * 16, acc[mf][nf], 36, wmma::mem_row_major);
        __syncwarp();

        const float* rowp  = patch + lane * 36;
        const float* biasp = smf + SM_BIAS + ch * 64 + nh * 32;
        #pragma unroll
        for (int c = 0; c < 32; c++) {
            float sc = rowp[c] - biasp[c];
            if (sc > bs) { bs = sc; bi = ch * 64 + nh * 32 + c; }
        }
        __syncthreads();
    }

    // merge the two n-halves per token (smem reuse of scores area)
    float* mS = smf + SM_SC;                 // [128][2] score
    int*   mI = (int*)(smf + SM_SC + 256);   // [128][2] code
    mS[(mw * 32 + lane) * 2 + nh] = bs;
    mI[(mw * 32 + lane) * 2 + nh] = bi;
    __syncthreads();
    if (tid < 128) {
        float s0 = mS[tid * 2], s1 = mS[tid * 2 + 1];
        int   c0 = mI[tid * 2], c1 = mI[tid * 2 + 1];
        int c = (s1 > s0 || (s1 == s0 && c1 < c0)) ? c1 : c0;
        int token = mt * 128 + tid;
        g_idx[token] = c;
        out[IDX_OFF + token] = (float)c;
    }
}

// ---------------- K2b: counts + segment-sum of z (reads z NCHW) -------------
__global__ void k_finalize(const float* __restrict__ z) {
    int n = blockIdx.x * 256 + threadIdx.x;     // 32768 threads
    int code = g_idx[n];
    atomicAdd(&g_counts[code], 1);
    int b = n >> 10, hw = n & 1023;
    const float* zp = z + (size_t)b * 65536 + hw;
    float* sw = g_sumw + (size_t)code * D_DIM;
    #pragma unroll
    for (int d = 0; d < 64; d++)
        atomicAdd(&sw[d], zp[(size_t)d * 1024]);
}

// ---------------- K3: gather z_q (NCHW) + commitment loss -------------------
__global__ void k_gather(const float* __restrict__ z, const float* __restrict__ emb,
                         float* __restrict__ out) {
    int gid = blockIdx.x * 256 + threadIdx.x;
    int b = gid >> 16, c = (gid >> 10) & 63, hw = gid & 1023;
    int n = (b << 10) | hw;
    int code = g_idx[n];
    float q  = __ldg(&emb[(size_t)code * D_DIM + c]);
    float zv = z[gid];
    float d  = q - zv;
    out[ZQ_OFF + gid] = zv + d;
    block_atomic_add(d * d, &g_loss);
}

// ---------------- K4a ----------------
__global__ void k_cs(const float* __restrict__ cs_in) {
    int k = blockIdx.x * 256 + threadIdx.x;
    float c = DECAYF * cs_in[k] + OMDF * (float)g_counts[k];
    g_cs[k] = c;
    block_atomic_add(c, &g_cssum);
}

// ---------------- K4b ----------------
__global__ void k_out(const float* __restrict__ ema_w, float* __restrict__ out) {
    int gid = blockIdx.x * 256 + threadIdx.x;
    int k = gid >> 6, d = gid & 63;
    float denom = g_cssum + KEPSF;
    float cn = (g_cs[k] + EPSF) / denom;
    float ew = DECAYF * ema_w[gid] + OMDF * g_sumw[gid];
    out[EMA_OFF + gid] = ew;
    out[EMB_OFF + gid] = ew / cn;
    if (d == 0)   out[CSN_OFF + k] = cn;
    if (gid == 0) out[LOSS_OFF] = BETAF * g_loss * (1.0f / 2097152.0f);
}

// ---------------- launch ----------------
extern "C" void kernel_launch(void* const* d_in, const int* in_sizes, int n_in,
                              void* d_out, int out_size) {
    const float* z      = (const float*)d_in[0];
    const float* emb    = (const float*)d_in[1];
    const float* ema_w  = (const float*)d_in[2];
    const float* cs_in  = (const float*)d_in[3];
    float* out = (float*)d_out;

    const int SMEM_MAIN = SM_TOTF * 4;   // 135168 B
    cudaFuncSetAttribute(k_main, cudaFuncAttributeMaxDynamicSharedMemorySize, SMEM_MAIN);

    k_prep    <<<12320, 256>>>(z, emb);
    k_main    <<<  256, 256, SMEM_MAIN>>>(out);
    k_finalize<<<  128, 256>>>(z);
    k_gather  <<< 8192, 256>>>(z, emb, out);
    k_cs      <<<   32, 256>>>(cs_in);
    k_out     <<< 2048, 256>>>(ema_w, out);
}